// round 14
// baseline (speedup 1.0000x reference)
#include <cuda_runtime.h>
#include <cstdint>

// GroupedEmbeddingBag: T tables, weights [V, D] fp32.
// values: [T, L] int32, offsets: [T, B+1] int32, out: [B, T*D] fp32.
// PERSISTENT one-warp CTAs (grid = 148*28) pulling bags off a global atomic
// counter; the next-bag grab is issued before processing the current bag so
// its latency hides under the gather work. Per bag: double-buffered batches
// of 6 row-gathers (ld.global.nc.v2.b64, L1::no_allocate) accumulated with
// packed add.rn.f32x2 (2 adds/row/thread instead of 4). Indices for a
// 60-row chunk come from two coalesced LDG.32s + shfl broadcast.

static constexpr int T = 8;
static constexpr int V = 100000;
static constexpr int D = 128;
static constexpr int B = 4096;
static constexpr int NBAGS = T * B;           // 32768

static constexpr int NUM_SMS = 148;
static constexpr int CTAS_PER_SM = 28;

__device__ int g_bag_counter;

__global__ void reset_counter_kernel() { g_bag_counter = 0; }

__device__ __forceinline__ void ldg_row16(const void* p,
                                          unsigned long long& a,
                                          unsigned long long& b) {
    asm volatile("ld.global.nc.L1::no_allocate.v2.b64 {%0,%1}, [%2];"
                 : "=l"(a), "=l"(b) : "l"(p));
}

__device__ __forceinline__ void add_f32x2(unsigned long long& acc,
                                          unsigned long long v) {
    asm volatile("add.rn.f32x2 %0, %0, %1;" : "+l"(acc) : "l"(v));
}

__global__ void __launch_bounds__(32, CTAS_PER_SM)
grouped_embedding_bag_kernel(const int* __restrict__ values,
                             const int* __restrict__ offsets,
                             const float* __restrict__ weights,
                             float* __restrict__ out,
                             int L)
{
    const int lane = threadIdx.x;
    const unsigned lane_off = (unsigned)lane * 16u;

    // Grab first bag.
    int bag0 = 0;
    if (lane == 0) bag0 = atomicAdd(&g_bag_counter, 1);
    int bag = __shfl_sync(0xffffffffu, bag0, 0);

    while (bag < NBAGS) {
        // Issue the next-bag grab now; consume its result after processing.
        int nbag0 = 0;
        if (lane == 0) nbag0 = atomicAdd(&g_bag_counter, 1);

        const int t = bag / B;
        const int b = bag - t * B;

        const int s = offsets[t * (B + 1) + b];
        const int e = offsets[t * (B + 1) + b + 1];

        const int* vals = values + t * L;
        // Per-table base; per-row byte offset fits in u32 (idx*512 <= 51.2MB).
        const char* __restrict__ Wb =
            reinterpret_cast<const char*>(weights + (long long)t * V * D);

        // Packed f32x2 accumulators: [0]=(x,y), [1]=(z,w); two banks.
        unsigned long long accA0 = 0, accA1 = 0, accB0 = 0, accB1 = 0;

        int i = s;
        while (i < e) {
            const int m = min(60, e - i);          // chunk: 10 batches of 6
            const int my0 = (lane      < m) ? vals[i + lane]      : 0;
            const int my1 = (lane + 32 < m) ? vals[i + lane + 32] : 0;

            auto get_idx = [&](int r) -> unsigned {
                const int rc  = (r < m) ? r : (m - 1);     // clamp tail
                const int v32 = (rc < 32) ? my0 : my1;
                return (unsigned)__shfl_sync(0xffffffffu, v32, rc & 31);
            };
            auto gather6 = [&](unsigned long long (*buf)[2], int j) {
                #pragma unroll
                for (int k = 0; k < 6; k++)
                    ldg_row16(Wb + get_idx(j + k) * 512u + lane_off,
                              buf[k][0], buf[k][1]);
            };
            auto consume6 = [&](unsigned long long (*buf)[2], int j) {
                #pragma unroll
                for (int k = 0; k < 6; k += 2) {
                    if (j + k < m) {
                        add_f32x2(accA0, buf[k][0]);
                        add_f32x2(accA1, buf[k][1]);
                    }
                    if (j + k + 1 < m) {
                        add_f32x2(accB0, buf[k + 1][0]);
                        add_f32x2(accB1, buf[k + 1][1]);
                    }
                }
            };

            unsigned long long bufA[6][2], bufB[6][2];
            gather6(bufA, 0);
            for (int j = 0; j < m; j += 12) {
                if (j + 6 < m)  gather6(bufB, j + 6);
                consume6(bufA, j);
                if (j + 12 < m) gather6(bufA, j + 12);
                if (j + 6 < m)  consume6(bufB, j + 6);
            }
            i += m;
        }

        add_f32x2(accA0, accB0);
        add_f32x2(accA1, accB1);

        // Unpack and store: out[b, t*D + lane*4 ...], 512B coalesced per warp.
        float4 r;
        {
            unsigned lo, hi;
            asm("mov.b64 {%0,%1}, %2;" : "=r"(lo), "=r"(hi) : "l"(accA0));
            r.x = __uint_as_float(lo); r.y = __uint_as_float(hi);
            asm("mov.b64 {%0,%1}, %2;" : "=r"(lo), "=r"(hi) : "l"(accA1));
            r.z = __uint_as_float(lo); r.w = __uint_as_float(hi);
        }
        float4* dst = reinterpret_cast<float4*>(out + (long long)b * (T * D) + t * D);
        dst[lane] = r;

        bag = __shfl_sync(0xffffffffu, nbag0, 0);
    }
}

extern "C" void kernel_launch(void* const* d_in, const int* in_sizes, int n_in,
                              void* d_out, int out_size)
{
    const int*   values  = (const int*)d_in[0];    // [T, L] int32
    const int*   offsets = (const int*)d_in[1];    // [T, B+1] int32
    const float* weights = (const float*)d_in[2];  // [T, V, D] fp32
    float* out = (float*)d_out;                    // [B, T*D] fp32

    const int L = in_sizes[0] / T;

    reset_counter_kernel<<<1, 1>>>();
    grouped_embedding_bag_kernel<<<NUM_SMS * CTAS_PER_SM, 32>>>(
        values, offsets, weights, out, L);
}

// round 15
// speedup vs baseline: 1.4204x; 1.4204x over previous
#include <cuda_runtime.h>
#include <cstdint>

// GroupedEmbeddingBag via uniform row-range decomposition.
// values: [T, L] int32, offsets: [T, B+1] int32, weights: [T, V, D] fp32,
// out: [B, T*D] fp32.
// Each warp owns a fixed 128-row contiguous range of one table's id stream
// (perfect load balance; one startup per ~2.5 bags). Bag boundaries are
// resolved during consumption: interior segments -> plain float4 store,
// range-boundary segments -> atomicAdd onto a zero-initialized output.
// Start bag per range is precomputed by a binary-search kernel.
// Gather engine (R13-proven): float4 ld.global.nc.L1::no_allocate,
// double-buffered batches of 4 rows, indices staged in smem (512B/warp).

static constexpr int T = 8;
static constexpr int V = 100000;
static constexpr int D = 128;
static constexpr int B = 4096;
static constexpr int RANGE = 128;               // rows per warp
static constexpr int MAX_RANGES = 16384;        // capacity (actual: 12800)

__device__ int g_start_bag[MAX_RANGES];

// ---------------- aux kernel 1: zero the output ----------------
__global__ void zero_out_kernel(float4* out4, int n4) {
    const int i = blockIdx.x * blockDim.x + threadIdx.x;
    if (i < n4) out4[i] = make_float4(0.f, 0.f, 0.f, 0.f);
}

// ---------------- aux kernel 2: start bag per range ----------------
// b = #{ j in [1,B] : offs[j] <= r0 }  (matches searchsorted(offs[1:], r0, right))
__global__ void find_start_bags_kernel(const int* __restrict__ offsets,
                                       int ranges_per_table, int n_ranges) {
    const int w = blockIdx.x * blockDim.x + threadIdx.x;
    if (w >= n_ranges) return;
    const int t  = w / ranges_per_table;
    const int r0 = (w - t * ranges_per_table) * RANGE;
    const int* offs = offsets + t * (B + 1);
    int lo = 0, hi = B;                 // count in [0, B]
    while (lo < hi) {                   // first j (1-based idx = mid+1) with offs > r0
        const int mid = (lo + hi) >> 1;
        if (offs[mid + 1] <= r0) lo = mid + 1; else hi = mid;
    }
    g_start_bag[w] = lo;
}

// ---------------- main kernel ----------------
__device__ __forceinline__ float4 ldg_na(const void* p) {
    float4 v;
    asm volatile("ld.global.nc.L1::no_allocate.v4.f32 {%0,%1,%2,%3}, [%4];"
                 : "=f"(v.x), "=f"(v.y), "=f"(v.z), "=f"(v.w)
                 : "l"(p));
    return v;
}

__global__ void __launch_bounds__(32)
grouped_embedding_bag_kernel(const int* __restrict__ values,
                             const int* __restrict__ offsets,
                             const float* __restrict__ weights,
                             float* __restrict__ out,
                             int L, int ranges_per_table)
{
    __shared__ int sidx[RANGE];

    const int w    = blockIdx.x;
    const int lane = threadIdx.x;

    const int t  = w / ranges_per_table;
    const int r0 = (w - t * ranges_per_table) * RANGE;
    const int r1 = r0 + RANGE;

    const int* offs = offsets + t * (B + 1);
    const int* vals = values + t * L + r0;

    // Stage this range's 128 indices in smem (4 coalesced loads, issued together).
    #pragma unroll
    for (int q = 0; q < 4; q++) sidx[lane + 32 * q] = vals[lane + 32 * q];
    __syncwarp();

    // Per-table weight base; row byte offset fits in u32 (idx*512 <= 51.2MB).
    const char* __restrict__ Wb =
        reinterpret_cast<const char*>(weights + (long long)t * V * D);
    const unsigned lane_off = (unsigned)lane * 16u;

    int  b_cur = g_start_bag[w];
    int  e_cur = offs[b_cur + 1];       // > r0 by construction
    bool first_seg = true;

    float4 accA = make_float4(0.f, 0.f, 0.f, 0.f);
    float4 accB = make_float4(0.f, 0.f, 0.f, 0.f);

    auto flush = [&](bool atomic_) {
        float* dst = out + (long long)b_cur * (T * D) + t * D + lane * 4;
        const float vx = accA.x + accB.x, vy = accA.y + accB.y;
        const float vz = accA.z + accB.z, vw = accA.w + accB.w;
        if (atomic_) {
            atomicAdd(dst + 0, vx); atomicAdd(dst + 1, vy);
            atomicAdd(dst + 2, vz); atomicAdd(dst + 3, vw);
        } else {
            *reinterpret_cast<float4*>(dst) = make_float4(vx, vy, vz, vw);
        }
        accA = make_float4(0.f, 0.f, 0.f, 0.f);
        accB = make_float4(0.f, 0.f, 0.f, 0.f);
    };

    auto gather4 = [&](float4* buf, int j) {
        #pragma unroll
        for (int k = 0; k < 4; k++) {
            const unsigned idx = (unsigned)sidx[j + k];
            buf[k] = ldg_na(Wb + idx * 512u + lane_off);
        }
    };
    auto consume4 = [&](const float4* buf, int j) {
        #pragma unroll
        for (int k = 0; k < 4; k++) {
            const int r = r0 + j + k;
            if (r >= e_cur) {                       // rare: bag ended inside range
                do {
                    flush(first_seg);               // in-loop flush is never last
                    first_seg = false;
                    b_cur++;
                    e_cur = offs[b_cur + 1];
                } while (r >= e_cur);
            }
            if (k & 1) {
                accB.x += buf[k].x; accB.y += buf[k].y;
                accB.z += buf[k].z; accB.w += buf[k].w;
            } else {
                accA.x += buf[k].x; accA.y += buf[k].y;
                accA.z += buf[k].z; accA.w += buf[k].w;
            }
        }
    };

    // Double-buffered pipeline over 32 batches of 4 rows (RANGE=128 exact).
    float4 bufA[4], bufB[4];
    gather4(bufA, 0);
    for (int j = 0; j < RANGE; j += 8) {
        if (j + 4 < RANGE) gather4(bufB, j + 4);
        consume4(bufA, j);
        if (j + 8 < RANGE) gather4(bufA, j + 8);
        consume4(bufB, j + 4);
    }

    // Final segment: boundary iff first (left-cut) or bag extends past r1.
    flush(first_seg || e_cur > r1);
}

extern "C" void kernel_launch(void* const* d_in, const int* in_sizes, int n_in,
                              void* d_out, int out_size)
{
    const int*   values  = (const int*)d_in[0];    // [T, L] int32
    const int*   offsets = (const int*)d_in[1];    // [T, B+1] int32
    const float* weights = (const float*)d_in[2];  // [T, V, D] fp32
    float* out = (float*)d_out;                    // [B, T*D] fp32

    const int L = in_sizes[0] / T;
    const int ranges_per_table = L / RANGE;        // 1600 (L divisible by 128)
    const int n_ranges = T * ranges_per_table;     // 12800

    // 1) zero output
    const int n4 = out_size / 4;                   // 1,048,576 float4
    zero_out_kernel<<<(n4 + 255) / 256, 256>>>((float4*)out, n4);

    // 2) start bag per range
    find_start_bags_kernel<<<(n_ranges + 127) / 128, 128>>>(offsets,
                                                            ranges_per_table,
                                                            n_ranges);

    // 3) main gather/pool
    grouped_embedding_bag_kernel<<<n_ranges, 32>>>(values, offsets, weights,
                                                   out, L, ranges_per_table);
}